// round 1
// baseline (speedup 1.0000x reference)
#include <cuda_runtime.h>
#include <cuda_bf16.h>

// RBFKernel: out[b,n,m] = exp(-(x1[b,n]-x2[b,m])^2 / (2*scale^2))
// B=4, N1=N2=8192, D=1. Output 268M fp32 (~1.07 GB) -> store-BW bound.
// exp computed on the FMA pipe (no MUFU) to avoid the 0.5 op/cyc/SM EX2 ceiling.

#define RBF_B   4
#define RBF_N1  8192
#define RBF_N2  8192
#define RBF_THREADS 256

// Fast 2^x-based exp of (d*d*k), k = -log2(e)/(2*s^2).
// Degree-5 Taylor of 2^f on [-0.5, 0.5]: max rel err ~2.4e-6.
__device__ __forceinline__ float rbf_exp(float d, float k) {
    float y = d * d * k;                      // y <= 0
    y = fmaxf(y, -125.0f);                    // keep exponent-bit trick in normal range
    float z = y + 12582912.0f;                // round-to-nearest-int magic (1.5*2^23)
    int   n = __float_as_int(z) - 0x4B400000; // integer part
    float f = y - (z - 12582912.0f);          // frac in [-0.5, 0.5]
    float p =              1.33335581e-3f;
    p = fmaf(p, f,         9.61812910e-3f);
    p = fmaf(p, f,         5.55041087e-2f);
    p = fmaf(p, f,         2.40226507e-1f);
    p = fmaf(p, f,         6.93147181e-1f);
    p = fmaf(p, f,         1.0f);             // p = 2^f in [0.707, 1.415)
    return __int_as_float(__float_as_int(p) + (n << 23)); // p * 2^n
}

__global__ void __launch_bounds__(RBF_THREADS)
rbf_kernel(const float* __restrict__ x1,
           const float* __restrict__ x2,
           const float* __restrict__ scale,
           float* __restrict__ out) {
    const int row = blockIdx.x;          // 0 .. B*N1-1
    const int b   = row >> 13;           // row / 8192
    const float a = __ldg(&x1[row]);
    const float s = __ldg(&scale[0]);
    const float k = -0.72134752044f / (s * s);   // -log2(e)/2 / s^2

    const float4* __restrict__ xv = (const float4*)(x2 + (size_t)b * RBF_N2);
    float4* __restrict__ ov = (float4*)(out + (size_t)row * RBF_N2);

    #pragma unroll
    for (int j = 0; j < (RBF_N2 / 4) / RBF_THREADS; ++j) {
        const int idx = j * RBF_THREADS + threadIdx.x;
        const float4 v = xv[idx];
        float4 r;
        r.x = rbf_exp(a - v.x, k);
        r.y = rbf_exp(a - v.y, k);
        r.z = rbf_exp(a - v.z, k);
        r.w = rbf_exp(a - v.w, k);
        ov[idx] = r;
    }
}

extern "C" void kernel_launch(void* const* d_in, const int* in_sizes, int n_in,
                              void* d_out, int out_size) {
    const float* x1    = (const float*)d_in[0];
    const float* x2    = (const float*)d_in[1];
    const float* scale = (const float*)d_in[2];
    float* out = (float*)d_out;

    rbf_kernel<<<RBF_B * RBF_N1, RBF_THREADS>>>(x1, x2, scale, out);
}